// round 3
// baseline (speedup 1.0000x reference)
#include <cuda_runtime.h>
#include <cstdint>

// Chamfer distance: pred [N,3], gt [M,4] (first 3 cols used)
// out = mean_n min_m |p_n-g_m|^2 + mean_m min_n |p_n-g_m|^2  (d2 clamped at 0;
// clamp commutes with min since max(.,0) is monotone).
//
// d2 = p2 + 2*(0.5*|b|^2 - dot(a,b)).  Inner kernel computes t = 0.5|b|^2 - a.b
// for all pairs with packed fma.rn.f32x2 (two B points per op), keeps running
// packed mins. p2, the *2, the clamp and the mean are folded into reduce1.

#define TPB      256
#define APT      2                 // A points per thread
#define ABLK     (TPB * APT)       // 512 A points per block
#define BSPLIT   74                // 40*74*2 = 5920 blocks = 8 waves @5/SM, 10 @4/SM
#define MAXN     20480             // >= 20000, multiple of TPB
#define TILE_PTS 280               // >= ceil(20000/74)=271 padded to mult of 8
#define RED1_BLOCKS (2 * MAXN / TPB)   // 160

__device__ float g_pmin[2][BSPLIT][MAXN];
__device__ float g_bsum[RED1_BLOCKS];

#define F32_INF __int_as_float(0x7f800000)

// Load 16B from smem as two b64 (each an f32x2 pair), immediate offset.
#define LDS_V2U64(v0, v1, base, OFF)                                     \
    asm volatile("ld.shared.v2.u64 {%0,%1}, [%2+" #OFF "];"              \
                 : "=l"(v0), "=l"(v1) : "r"(base))

// t01 = fma(nx, x01, h01); t01 = fma(ny, y01, t01); t01 = fma(nz, z01, t01);
// then unpack halves. Operand map: %2=nx %3=x01 %4=ny %5=y01 %6=nz %7=z01 %8=h01.
// The mov.b64 {lo,hi} is a register-pair alias ptxas elides.
#define PAIR_DIST(lo, hi, nx, ny, nz, x01, y01, z01, h01)                \
    asm("{\n\t.reg .b64 t;\n\t"                                          \
        "fma.rn.f32x2 t, %2, %3, %8;\n\t"                                \
        "fma.rn.f32x2 t, %4, %5, t;\n\t"                                 \
        "fma.rn.f32x2 t, %6, %7, t;\n\t"                                 \
        "mov.b64 {%0,%1}, t;\n\t}"                                       \
        : "=f"(lo), "=f"(hi)                                             \
        : "l"(nx), "l"(x01), "l"(ny), "l"(y01), "l"(nz), "l"(z01), "l"(h01))

__global__ __launch_bounds__(TPB)
void cd_min_kernel(const float* __restrict__ pred, int nP,
                   const float* __restrict__ gt,   int nG)
{
    const int dir = blockIdx.z;                 // 0: A=pred,B=gt ; 1: A=gt,B=pred
    const float* __restrict__ A = (dir == 0) ? pred : gt;
    const float* __restrict__ B = (dir == 0) ? gt   : pred;
    const int sA = (dir == 0) ? 3 : 4;
    const int sB = (dir == 0) ? 4 : 3;
    const int nA = (dir == 0) ? nP : nG;
    const int nB = (dir == 0) ? nG : nP;

    // Interleaved tile: per 2 B points, 32 bytes: {x0,x1,y0,y1, z0,z1,h0,h1}
    __shared__ __align__(16) float tileF[TILE_PTS * 4];

    // Per-thread A points (strided by TPB for coalesced loads), negated+packed.
    const int a0 = blockIdx.x * ABLK + threadIdx.x;
    unsigned long long NX[APT], NY[APT], NZ[APT];
    #pragma unroll
    for (int k = 0; k < APT; k++) {
        const int a = a0 + k * TPB;
        float nax = 0.f, nay = 0.f, naz = 0.f;
        if (a < nA) {
            nax = -A[a * sA + 0];
            nay = -A[a * sA + 1];
            naz = -A[a * sA + 2];
        }
        asm("mov.b64 %0, {%1,%1};" : "=l"(NX[k]) : "f"(nax));
        asm("mov.b64 %0, {%1,%1};" : "=l"(NY[k]) : "f"(nay));
        asm("mov.b64 %0, {%1,%1};" : "=l"(NZ[k]) : "f"(naz));
    }

    const int chunk = (nB + gridDim.y - 1) / gridDim.y;
    const int b0 = blockIdx.y * chunk;
    const int b1 = min(b0 + chunk, nB);
    const int cnt = b1 - b0;                    // 1..TILE_PTS
    const int padded = (cnt + 7) & ~7;          // pad with copies of last point

    // Fill tile (scalar stores; tiny vs. the O(A*B) loop)
    for (int j = threadIdx.x; j < padded; j += TPB) {
        const int bi = b0 + min(j, cnt - 1);
        const float bx = B[bi * sB + 0];
        const float by = B[bi * sB + 1];
        const float bz = B[bi * sB + 2];
        const float h = 0.5f * (bx * bx + by * by + bz * bz);
        const int g = j >> 1, l = j & 1, o = g * 8 + l;
        tileF[o + 0] = bx;
        tileF[o + 2] = by;
        tileF[o + 4] = bz;
        tileF[o + 6] = h;
    }
    __syncthreads();

    float mlo[APT], mhi[APT];
    #pragma unroll
    for (int k = 0; k < APT; k++) { mlo[k] = F32_INF; mhi[k] = F32_INF; }

    unsigned int saddr = (unsigned int)__cvta_generic_to_shared(tileF);
    const int ngroups = padded >> 1;            // multiple of 4

    for (int g = 0; g < ngroups; g += 4) {
        unsigned long long X01, Y01, Z01, H01;
        float lo, hi;

        #define GROUP(OX, OZ)                                                \
            LDS_V2U64(X01, Y01, saddr, OX);                                  \
            LDS_V2U64(Z01, H01, saddr, OZ);                                  \
            _Pragma("unroll")                                                \
            for (int k = 0; k < APT; k++) {                                  \
                PAIR_DIST(lo, hi, NX[k], NY[k], NZ[k], X01, Y01, Z01, H01);  \
                mlo[k] = fminf(mlo[k], lo);                                  \
                mhi[k] = fminf(mhi[k], hi);                                  \
            }

        GROUP(0, 16)
        GROUP(32, 48)
        GROUP(64, 80)
        GROUP(96, 112)
        #undef GROUP

        saddr += 128;
    }

    #pragma unroll
    for (int k = 0; k < APT; k++) {
        const int a = a0 + k * TPB;
        if (a < nA)
            g_pmin[dir][blockIdx.y][a] = fminf(mlo[k], mhi[k]);
    }
}

__global__ __launch_bounds__(TPB)
void cd_reduce1(const float* __restrict__ pred, int nP,
                const float* __restrict__ gt,   int nG)
{
    const int t   = blockIdx.x * TPB + threadIdx.x;
    const int dir = t / MAXN;
    const int i   = t - dir * MAXN;

    float v = 0.f;
    const int nA = (dir == 0) ? nP : nG;
    if (i < nA) {
        const float* __restrict__ Aptr = (dir == 0) ? pred : gt;
        const int sA = (dir == 0) ? 3 : 4;
        const float ax = Aptr[i * sA + 0];
        const float ay = Aptr[i * sA + 1];
        const float az = Aptr[i * sA + 2];
        const float p2 = ax * ax + ay * ay + az * az;
        float mn = g_pmin[dir][0][i];
        #pragma unroll
        for (int s = 1; s < BSPLIT; s++)
            mn = fminf(mn, g_pmin[dir][s][i]);
        const float d2 = fmaxf(fmaf(2.f, mn, p2), 0.f);
        v = d2 / (float)nA;                 // fold per-direction mean
    }

    __shared__ float sm[TPB];
    sm[threadIdx.x] = v;
    __syncthreads();
    for (int s = TPB / 2; s > 0; s >>= 1) {
        if (threadIdx.x < s) sm[threadIdx.x] += sm[threadIdx.x + s];
        __syncthreads();
    }
    if (threadIdx.x == 0)
        g_bsum[blockIdx.x] = sm[0];
}

__global__ __launch_bounds__(TPB)
void cd_reduce2(float* __restrict__ out, int nblocks)
{
    float v = 0.f;
    for (int i = threadIdx.x; i < nblocks; i += TPB)
        v += g_bsum[i];

    __shared__ float sm[TPB];
    sm[threadIdx.x] = v;
    __syncthreads();
    for (int s = TPB / 2; s > 0; s >>= 1) {
        if (threadIdx.x < s) sm[threadIdx.x] += sm[threadIdx.x + s];
        __syncthreads();
    }
    if (threadIdx.x == 0)
        out[0] = sm[0];
}

extern "C" void kernel_launch(void* const* d_in, const int* in_sizes, int n_in,
                              void* d_out, int out_size)
{
    // pred has 3 columns (smaller buffer), gt has 4. Robust to input order.
    const float* pred;
    const float* gt;
    int szP, szG;
    if (in_sizes[0] <= in_sizes[1]) {
        pred = (const float*)d_in[0]; szP = in_sizes[0];
        gt   = (const float*)d_in[1]; szG = in_sizes[1];
    } else {
        pred = (const float*)d_in[1]; szP = in_sizes[1];
        gt   = (const float*)d_in[0]; szG = in_sizes[0];
    }
    const int nP = szP / 3;
    const int nG = szG / 4;

    const int nmax = (nP > nG) ? nP : nG;
    dim3 grid((nmax + ABLK - 1) / ABLK, BSPLIT, 2);
    cd_min_kernel<<<grid, TPB>>>(pred, nP, gt, nG);
    cd_reduce1<<<RED1_BLOCKS, TPB>>>(pred, nP, gt, nG);
    cd_reduce2<<<1, TPB>>>((float*)d_out, RED1_BLOCKS);
}

// round 4
// speedup vs baseline: 1.0792x; 1.0792x over previous
#include <cuda_runtime.h>
#include <cstdint>

// Chamfer distance: pred [N,3], gt [M,4] (first 3 cols used)
// out = mean_n min_m |p_n-g_m|^2 + mean_m min_n |p_n-g_m|^2  (d2 clamped at 0;
// clamp commutes with min since max(.,0) is monotone).
//
// d2 = p2 + 2*(0.5*|b|^2 - dot(a,b)).  Inner kernel computes t = 0.5|b|^2 - a.b
// for all pairs with packed fma.rn.f32x2 (two B points per op), keeps running
// packed mins. p2, the *2, the clamp and the mean are folded into reduce1.
//
// R3 ncu: L1tex (shared) path bound at 81.7%, fma only 57.8%. APT 2->4 halves
// LDS wavefronts per pair; FFMA2 pipe becomes the binding resource.

#define TPB      256
#define APT      4                 // A points per thread
#define ABLK     (TPB * APT)       // 1024 A points per block
#define BSPLIT   74                // 20*74*2 = 2960 blocks = 5 waves @4/SM, 4 @5/SM
#define MAXN     20480             // >= 20000, multiple of ABLK
#define TILE_PTS 280               // >= ceil(20000/74)=271 padded to mult of 8
#define RED1_BLOCKS (2 * MAXN / TPB)   // 160

__device__ float g_pmin[2][BSPLIT][MAXN];
__device__ float g_bsum[RED1_BLOCKS];

#define F32_INF __int_as_float(0x7f800000)

// Load 16B from smem as two b64 (each an f32x2 pair), immediate offset.
#define LDS_V2U64(v0, v1, base, OFF)                                     \
    asm volatile("ld.shared.v2.u64 {%0,%1}, [%2+" #OFF "];"              \
                 : "=l"(v0), "=l"(v1) : "r"(base))

// t01 = fma(nx, x01, h01); t01 = fma(ny, y01, t01); t01 = fma(nz, z01, t01);
// then unpack halves. Operand map: %2=nx %3=x01 %4=ny %5=y01 %6=nz %7=z01 %8=h01.
// The mov.b64 {lo,hi} is a register-pair alias ptxas elides.
#define PAIR_DIST(lo, hi, nx, ny, nz, x01, y01, z01, h01)                \
    asm("{\n\t.reg .b64 t;\n\t"                                          \
        "fma.rn.f32x2 t, %2, %3, %8;\n\t"                                \
        "fma.rn.f32x2 t, %4, %5, t;\n\t"                                 \
        "fma.rn.f32x2 t, %6, %7, t;\n\t"                                 \
        "mov.b64 {%0,%1}, t;\n\t}"                                       \
        : "=f"(lo), "=f"(hi)                                             \
        : "l"(nx), "l"(x01), "l"(ny), "l"(y01), "l"(nz), "l"(z01), "l"(h01))

__global__ __launch_bounds__(TPB)
void cd_min_kernel(const float* __restrict__ pred, int nP,
                   const float* __restrict__ gt,   int nG)
{
    const int dir = blockIdx.z;                 // 0: A=pred,B=gt ; 1: A=gt,B=pred
    const float* __restrict__ A = (dir == 0) ? pred : gt;
    const float* __restrict__ B = (dir == 0) ? gt   : pred;
    const int sA = (dir == 0) ? 3 : 4;
    const int sB = (dir == 0) ? 4 : 3;
    const int nA = (dir == 0) ? nP : nG;
    const int nB = (dir == 0) ? nG : nP;

    // Interleaved tile: per 2 B points, 32 bytes: {x0,x1,y0,y1, z0,z1,h0,h1}
    __shared__ __align__(16) float tileF[TILE_PTS * 4];

    // Per-thread A points (strided by TPB for coalesced loads), negated+packed.
    const int a0 = blockIdx.x * ABLK + threadIdx.x;
    unsigned long long NX[APT], NY[APT], NZ[APT];
    #pragma unroll
    for (int k = 0; k < APT; k++) {
        const int a = a0 + k * TPB;
        float nax = 0.f, nay = 0.f, naz = 0.f;
        if (a < nA) {
            nax = -A[a * sA + 0];
            nay = -A[a * sA + 1];
            naz = -A[a * sA + 2];
        }
        asm("mov.b64 %0, {%1,%1};" : "=l"(NX[k]) : "f"(nax));
        asm("mov.b64 %0, {%1,%1};" : "=l"(NY[k]) : "f"(nay));
        asm("mov.b64 %0, {%1,%1};" : "=l"(NZ[k]) : "f"(naz));
    }

    const int chunk = (nB + gridDim.y - 1) / gridDim.y;
    const int b0 = blockIdx.y * chunk;
    const int b1 = min(b0 + chunk, nB);
    const int cnt = b1 - b0;                    // 1..TILE_PTS
    const int padded = (cnt + 7) & ~7;          // pad with copies of last point

    // Fill tile (scalar stores; tiny vs. the O(A*B) loop)
    for (int j = threadIdx.x; j < padded; j += TPB) {
        const int bi = b0 + min(j, cnt - 1);
        const float bx = B[bi * sB + 0];
        const float by = B[bi * sB + 1];
        const float bz = B[bi * sB + 2];
        const float h = 0.5f * (bx * bx + by * by + bz * bz);
        const int g = j >> 1, l = j & 1, o = g * 8 + l;
        tileF[o + 0] = bx;
        tileF[o + 2] = by;
        tileF[o + 4] = bz;
        tileF[o + 6] = h;
    }
    __syncthreads();

    float mlo[APT], mhi[APT];
    #pragma unroll
    for (int k = 0; k < APT; k++) { mlo[k] = F32_INF; mhi[k] = F32_INF; }

    unsigned int saddr = (unsigned int)__cvta_generic_to_shared(tileF);
    const int ngroups = padded >> 1;            // multiple of 4

    for (int g = 0; g < ngroups; g += 4) {
        unsigned long long X01, Y01, Z01, H01;
        float lo, hi;

        #define GROUP(OX, OZ)                                                \
            LDS_V2U64(X01, Y01, saddr, OX);                                  \
            LDS_V2U64(Z01, H01, saddr, OZ);                                  \
            _Pragma("unroll")                                                \
            for (int k = 0; k < APT; k++) {                                  \
                PAIR_DIST(lo, hi, NX[k], NY[k], NZ[k], X01, Y01, Z01, H01);  \
                mlo[k] = fminf(mlo[k], lo);                                  \
                mhi[k] = fminf(mhi[k], hi);                                  \
            }

        GROUP(0, 16)
        GROUP(32, 48)
        GROUP(64, 80)
        GROUP(96, 112)
        #undef GROUP

        saddr += 128;
    }

    #pragma unroll
    for (int k = 0; k < APT; k++) {
        const int a = a0 + k * TPB;
        if (a < nA)
            g_pmin[dir][blockIdx.y][a] = fminf(mlo[k], mhi[k]);
    }
}

__global__ __launch_bounds__(TPB)
void cd_reduce1(const float* __restrict__ pred, int nP,
                const float* __restrict__ gt,   int nG)
{
    const int t   = blockIdx.x * TPB + threadIdx.x;
    const int dir = t / MAXN;
    const int i   = t - dir * MAXN;

    float v = 0.f;
    const int nA = (dir == 0) ? nP : nG;
    if (i < nA) {
        const float* __restrict__ Aptr = (dir == 0) ? pred : gt;
        const int sA = (dir == 0) ? 3 : 4;
        const float ax = Aptr[i * sA + 0];
        const float ay = Aptr[i * sA + 1];
        const float az = Aptr[i * sA + 2];
        const float p2 = ax * ax + ay * ay + az * az;
        float mn = g_pmin[dir][0][i];
        #pragma unroll
        for (int s = 1; s < BSPLIT; s++)
            mn = fminf(mn, g_pmin[dir][s][i]);
        const float d2 = fmaxf(fmaf(2.f, mn, p2), 0.f);
        v = d2 / (float)nA;                 // fold per-direction mean
    }

    __shared__ float sm[TPB];
    sm[threadIdx.x] = v;
    __syncthreads();
    for (int s = TPB / 2; s > 0; s >>= 1) {
        if (threadIdx.x < s) sm[threadIdx.x] += sm[threadIdx.x + s];
        __syncthreads();
    }
    if (threadIdx.x == 0)
        g_bsum[blockIdx.x] = sm[0];
}

__global__ __launch_bounds__(TPB)
void cd_reduce2(float* __restrict__ out, int nblocks)
{
    float v = 0.f;
    for (int i = threadIdx.x; i < nblocks; i += TPB)
        v += g_bsum[i];

    __shared__ float sm[TPB];
    sm[threadIdx.x] = v;
    __syncthreads();
    for (int s = TPB / 2; s > 0; s >>= 1) {
        if (threadIdx.x < s) sm[threadIdx.x] += sm[threadIdx.x + s];
        __syncthreads();
    }
    if (threadIdx.x == 0)
        out[0] = sm[0];
}

extern "C" void kernel_launch(void* const* d_in, const int* in_sizes, int n_in,
                              void* d_out, int out_size)
{
    // pred has 3 columns (smaller buffer), gt has 4. Robust to input order.
    const float* pred;
    const float* gt;
    int szP, szG;
    if (in_sizes[0] <= in_sizes[1]) {
        pred = (const float*)d_in[0]; szP = in_sizes[0];
        gt   = (const float*)d_in[1]; szG = in_sizes[1];
    } else {
        pred = (const float*)d_in[1]; szP = in_sizes[1];
        gt   = (const float*)d_in[0]; szG = in_sizes[0];
    }
    const int nP = szP / 3;
    const int nG = szG / 4;

    const int nmax = (nP > nG) ? nP : nG;
    dim3 grid((nmax + ABLK - 1) / ABLK, BSPLIT, 2);
    cd_min_kernel<<<grid, TPB>>>(pred, nP, gt, nG);
    cd_reduce1<<<RED1_BLOCKS, TPB>>>(pred, nP, gt, nG);
    cd_reduce2<<<1, TPB>>>((float*)d_out, RED1_BLOCKS);
}

// round 7
// speedup vs baseline: 1.2022x; 1.1140x over previous
#include <cuda_runtime.h>
#include <cstdint>

// Chamfer distance, one-pass shared distance matrix.
// t' = (0.5|a|^2 + 0.5|b|^2) - a.b = d^2/2.  Row mins (over gt) and col mins
// (over pred) reduce the SAME t' values -> half the FFMA2 work of the two-pass
// version. Col mins cross the warp via redux.sync.min.s32 on the float bits:
// exact for non-negative floats, and any negative t' (rounding noise) clamps
// to 0 in the epilogue regardless of which negative wins, so s32-min == fminf
// for this loss. redux.f32 is sm_100a-only (harness lowers via compute_100);
// redux.s32 is sm_80+.

#define TPB    256
#define APT    4                  // pred points per thread
#define ABLK   (TPB * APT)        // 1024 pred points per block
#define BT     136                // gt points per tile (mult of 8); 20*148=2960 blocks
#define MAXNP  20480              // >= 20000, multiple of ABLK
#define MAXNB  20128              // 148*136 >= 20000
#define MAX_BTILES (MAXNB / BT)   // 148
#define MAX_ATILES (MAXNP / ABLK) // 20
#define MAX_RED  ((MAXNP + TPB - 1) / TPB)   // 80

__device__ float g_rmin[MAX_BTILES][MAXNP];
__device__ int   g_cmin[MAX_ATILES][MAXNB];
__device__ float g_bsum[2 * MAX_RED];

#define F32_INF __int_as_float(0x7f800000)

#define LDS_V2U64(v0, v1, base, OFF)                                     \
    asm volatile("ld.shared.v2.u64 {%0,%1}, [%2+" #OFF "];"              \
                 : "=l"(v0), "=l"(v1) : "r"(base))

#define ADD2(out, a, b)                                                  \
    asm("add.rn.f32x2 %0, %1, %2;" : "=l"(out) : "l"(a), "l"(b))

// t = fma(nx, x01, hab); t = fma(ny, y01, t); t = fma(nz, z01, t); unpack.
#define PAIR_DIST(lo, hi, nx, ny, nz, x01, y01, z01, hab)                \
    asm("{\n\t.reg .b64 t;\n\t"                                          \
        "fma.rn.f32x2 t, %2, %3, %8;\n\t"                                \
        "fma.rn.f32x2 t, %4, %5, t;\n\t"                                 \
        "fma.rn.f32x2 t, %6, %7, t;\n\t"                                 \
        "mov.b64 {%0,%1}, t;\n\t}"                                       \
        : "=f"(lo), "=f"(hi)                                             \
        : "l"(nx), "l"(x01), "l"(ny), "l"(y01), "l"(nz), "l"(z01), "l"(hab))

__device__ __forceinline__ int redux_min_s32(int v) {
    int r;
    asm("redux.sync.min.s32 %0, %1, 0xffffffff;" : "=r"(r) : "r"(v));
    return r;
}

__global__ __launch_bounds__(TPB)
void cd_tile_kernel(const float* __restrict__ pred, int nP,
                    const float* __restrict__ gt,   int nG)
{
    __shared__ __align__(16) float tileF[BT * 4];  // per 2 B pts: {x0,x1,y0,y1,z0,z1,h0,h1}
    __shared__ int col_acc[8][BT];                 // per-warp col mins (each col written once)

    const int warp = threadIdx.x >> 5;
    const int lane = threadIdx.x & 31;

    // A = pred points, clamped-duplicate padding (dups harmless for col mins;
    // row writes guarded by original index).
    const int a0 = blockIdx.x * ABLK + threadIdx.x;
    unsigned long long NX[APT], NY[APT], NZ[APT], HA[APT];
    #pragma unroll
    for (int k = 0; k < APT; k++) {
        const int ac = min(a0 + k * TPB, nP - 1);
        const float ax = pred[ac * 3 + 0];
        const float ay = pred[ac * 3 + 1];
        const float az = pred[ac * 3 + 2];
        const float nax = -ax, nay = -ay, naz = -az;
        const float ha = 0.5f * (ax * ax + ay * ay + az * az);
        asm("mov.b64 %0, {%1,%1};" : "=l"(NX[k]) : "f"(nax));
        asm("mov.b64 %0, {%1,%1};" : "=l"(NY[k]) : "f"(nay));
        asm("mov.b64 %0, {%1,%1};" : "=l"(NZ[k]) : "f"(naz));
        asm("mov.b64 %0, {%1,%1};" : "=l"(HA[k]) : "f"(ha));
    }

    // B tile = gt points, clamped-duplicate padding.
    const int b0 = blockIdx.y * BT;
    for (int j = threadIdx.x; j < BT; j += TPB) {
        const int bi = min(b0 + j, nG - 1);
        const float bx = gt[bi * 4 + 0];
        const float by = gt[bi * 4 + 1];
        const float bz = gt[bi * 4 + 2];
        const float hb = 0.5f * (bx * bx + by * by + bz * bz);
        const int g = j >> 1, l = j & 1, o = g * 8 + l;
        tileF[o + 0] = bx;
        tileF[o + 2] = by;
        tileF[o + 4] = bz;
        tileF[o + 6] = hb;
    }
    __syncthreads();

    float mlo[APT], mhi[APT];
    #pragma unroll
    for (int k = 0; k < APT; k++) { mlo[k] = F32_INF; mhi[k] = F32_INF; }

    unsigned int saddr = (unsigned int)__cvta_generic_to_shared(tileF);

    for (int jb = 0; jb < BT; jb += 8) {
        unsigned long long X01, Y01, Z01, H01, HAB;
        float lo, hi;
        int cl, ch;

        #define GROUP(OX, OZ, JOFF)                                          \
        {                                                                    \
            LDS_V2U64(X01, Y01, saddr, OX);                                  \
            LDS_V2U64(Z01, H01, saddr, OZ);                                  \
            ADD2(HAB, H01, HA[0]);                                           \
            PAIR_DIST(lo, hi, NX[0], NY[0], NZ[0], X01, Y01, Z01, HAB);      \
            mlo[0] = fminf(mlo[0], lo);  mhi[0] = fminf(mhi[0], hi);         \
            cl = __float_as_int(lo);  ch = __float_as_int(hi);               \
            _Pragma("unroll")                                                \
            for (int k = 1; k < APT; k++) {                                  \
                ADD2(HAB, H01, HA[k]);                                       \
                PAIR_DIST(lo, hi, NX[k], NY[k], NZ[k], X01, Y01, Z01, HAB);  \
                mlo[k] = fminf(mlo[k], lo);  mhi[k] = fminf(mhi[k], hi);     \
                cl = min(cl, __float_as_int(lo));                            \
                ch = min(ch, __float_as_int(hi));                            \
            }                                                                \
            cl = redux_min_s32(cl);                                          \
            ch = redux_min_s32(ch);                                          \
            if (lane == 0) {                                                 \
                col_acc[warp][jb + JOFF + 0] = cl;                           \
                col_acc[warp][jb + JOFF + 1] = ch;                           \
            }                                                                \
        }

        GROUP(0,  16, 0)
        GROUP(32, 48, 2)
        GROUP(64, 80, 4)
        GROUP(96, 112, 6)
        #undef GROUP

        saddr += 128;
    }

    // Row partials: min over this B tile for each owned pred point.
    #pragma unroll
    for (int k = 0; k < APT; k++) {
        const int a = a0 + k * TPB;
        if (a < nP)
            g_rmin[blockIdx.y][a] = fminf(mlo[k], mhi[k]);
    }

    // Col partials: combine 8 warps, write this block's B range (int bits).
    __syncthreads();
    for (int j = threadIdx.x; j < BT; j += TPB) {
        int m = col_acc[0][j];
        #pragma unroll
        for (int w = 1; w < 8; w++)
            m = min(m, col_acc[w][j]);
        g_cmin[blockIdx.x][b0 + j] = m;     // padded slots written, never read
    }
}

__global__ __launch_bounds__(TPB)
void cd_red_rows(int nP, int nbt)
{
    const int i = blockIdx.x * TPB + threadIdx.x;
    float v = 0.f;
    if (i < nP) {
        float m = g_rmin[0][i];
        for (int t = 1; t < nbt; t++)
            m = fminf(m, g_rmin[t][i]);
        v = fmaxf(2.f * m, 0.f) / (float)nP;
    }
    __shared__ float sm[TPB];
    sm[threadIdx.x] = v;
    __syncthreads();
    for (int s = TPB / 2; s > 0; s >>= 1) {
        if (threadIdx.x < s) sm[threadIdx.x] += sm[threadIdx.x + s];
        __syncthreads();
    }
    if (threadIdx.x == 0) g_bsum[blockIdx.x] = sm[0];
}

__global__ __launch_bounds__(TPB)
void cd_red_cols(int nG, int nat, int outoff)
{
    const int j = blockIdx.x * TPB + threadIdx.x;
    float v = 0.f;
    if (j < nG) {
        int m = g_cmin[0][j];
        for (int t = 1; t < nat; t++)
            m = min(m, g_cmin[t][j]);
        v = fmaxf(2.f * __int_as_float(m), 0.f) / (float)nG;
    }
    __shared__ float sm[TPB];
    sm[threadIdx.x] = v;
    __syncthreads();
    for (int s = TPB / 2; s > 0; s >>= 1) {
        if (threadIdx.x < s) sm[threadIdx.x] += sm[threadIdx.x + s];
        __syncthreads();
    }
    if (threadIdx.x == 0) g_bsum[outoff + blockIdx.x] = sm[0];
}

__global__ __launch_bounds__(TPB)
void cd_final(float* __restrict__ out, int n)
{
    float v = 0.f;
    for (int i = threadIdx.x; i < n; i += TPB)
        v += g_bsum[i];
    __shared__ float sm[TPB];
    sm[threadIdx.x] = v;
    __syncthreads();
    for (int s = TPB / 2; s > 0; s >>= 1) {
        if (threadIdx.x < s) sm[threadIdx.x] += sm[threadIdx.x + s];
        __syncthreads();
    }
    if (threadIdx.x == 0) out[0] = sm[0];
}

extern "C" void kernel_launch(void* const* d_in, const int* in_sizes, int n_in,
                              void* d_out, int out_size)
{
    // pred has 3 columns (smaller buffer), gt has 4. Robust to input order.
    const float* pred;
    const float* gt;
    int szP, szG;
    if (in_sizes[0] <= in_sizes[1]) {
        pred = (const float*)d_in[0]; szP = in_sizes[0];
        gt   = (const float*)d_in[1]; szG = in_sizes[1];
    } else {
        pred = (const float*)d_in[1]; szP = in_sizes[1];
        gt   = (const float*)d_in[0]; szG = in_sizes[0];
    }
    const int nP = szP / 3;
    const int nG = szG / 4;

    const int atiles = (nP + ABLK - 1) / ABLK;      // 20
    const int btiles = (nG + BT - 1) / BT;          // 148

    dim3 grid(atiles, btiles);
    cd_tile_kernel<<<grid, TPB>>>(pred, nP, gt, nG);

    const int redA = (nP + TPB - 1) / TPB;
    const int redB = (nG + TPB - 1) / TPB;
    cd_red_rows<<<redA, TPB>>>(nP, btiles);
    cd_red_cols<<<redB, TPB>>>(nG, atiles, redA);
    cd_final<<<1, TPB>>>((float*)d_out, redA + redB);
}

// round 8
// speedup vs baseline: 1.2483x; 1.0384x over previous
#include <cuda_runtime.h>
#include <cstdint>

// Chamfer distance, one-pass shared distance matrix.
// t' = (0.5|a|^2 + 0.5|b|^2) - a.b = d^2/2.  Row mins (over gt) and col mins
// (over pred) reduce the SAME t' values. Col mins cross the warp via
// redux.sync.min.s32 on the float bits: exact for non-negative floats, and any
// negative t' (rounding noise) clamps to 0 in the epilogue regardless of which
// negative wins. redux.s32 is sm_80+ (redux.f32 rejected at compute_100).
//
// R7: 103 us total, ~88 us tile + ~15 us epilogue. R8: BT 136->272 (halves
// partial-min traffic, 20x74=1480 blocks = exactly 2 waves @5/SM) and fused
// row/col reduction kernel (one less launch).

#define TPB    256
#define APT    4                  // pred points per thread
#define ABLK   (TPB * APT)        // 1024 pred points per block
#define BT     272                // gt points per tile (mult of 8); 74 tiles
#define MAXNP  20480              // >= 20000, multiple of ABLK
#define MAXNB  20128              // 74*272 >= 20000
#define MAX_BTILES (MAXNB / BT)   // 74
#define MAX_ATILES (MAXNP / ABLK) // 20
#define MAX_RED  ((MAXNP + TPB - 1) / TPB)   // 80

__device__ float g_rmin[MAX_BTILES][MAXNP];
__device__ int   g_cmin[MAX_ATILES][MAXNB];
__device__ float g_bsum[2 * MAX_RED];

#define F32_INF __int_as_float(0x7f800000)

#define LDS_V2U64(v0, v1, base, OFF)                                     \
    asm volatile("ld.shared.v2.u64 {%0,%1}, [%2+" #OFF "];"              \
                 : "=l"(v0), "=l"(v1) : "r"(base))

#define ADD2(out, a, b)                                                  \
    asm("add.rn.f32x2 %0, %1, %2;" : "=l"(out) : "l"(a), "l"(b))

// t = fma(nx, x01, hab); t = fma(ny, y01, t); t = fma(nz, z01, t); unpack.
#define PAIR_DIST(lo, hi, nx, ny, nz, x01, y01, z01, hab)                \
    asm("{\n\t.reg .b64 t;\n\t"                                          \
        "fma.rn.f32x2 t, %2, %3, %8;\n\t"                                \
        "fma.rn.f32x2 t, %4, %5, t;\n\t"                                 \
        "fma.rn.f32x2 t, %6, %7, t;\n\t"                                 \
        "mov.b64 {%0,%1}, t;\n\t}"                                       \
        : "=f"(lo), "=f"(hi)                                             \
        : "l"(nx), "l"(x01), "l"(ny), "l"(y01), "l"(nz), "l"(z01), "l"(hab))

__device__ __forceinline__ int redux_min_s32(int v) {
    int r;
    asm("redux.sync.min.s32 %0, %1, 0xffffffff;" : "=r"(r) : "r"(v));
    return r;
}

__global__ __launch_bounds__(TPB)
void cd_tile_kernel(const float* __restrict__ pred, int nP,
                    const float* __restrict__ gt,   int nG)
{
    __shared__ __align__(16) float tileF[BT * 4];  // per 2 B pts: {x0,x1,y0,y1,z0,z1,h0,h1}
    __shared__ int col_acc[8][BT];                 // per-warp col mins (each col written once)

    const int warp = threadIdx.x >> 5;
    const int lane = threadIdx.x & 31;

    // A = pred points, clamped-duplicate padding (dups harmless for col mins;
    // row writes guarded by original index).
    const int a0 = blockIdx.x * ABLK + threadIdx.x;
    unsigned long long NX[APT], NY[APT], NZ[APT], HA[APT];
    #pragma unroll
    for (int k = 0; k < APT; k++) {
        const int ac = min(a0 + k * TPB, nP - 1);
        const float ax = pred[ac * 3 + 0];
        const float ay = pred[ac * 3 + 1];
        const float az = pred[ac * 3 + 2];
        const float nax = -ax, nay = -ay, naz = -az;
        const float ha = 0.5f * (ax * ax + ay * ay + az * az);
        asm("mov.b64 %0, {%1,%1};" : "=l"(NX[k]) : "f"(nax));
        asm("mov.b64 %0, {%1,%1};" : "=l"(NY[k]) : "f"(nay));
        asm("mov.b64 %0, {%1,%1};" : "=l"(NZ[k]) : "f"(naz));
        asm("mov.b64 %0, {%1,%1};" : "=l"(HA[k]) : "f"(ha));
    }

    // B tile = gt points, clamped-duplicate padding.
    const int b0 = blockIdx.y * BT;
    for (int j = threadIdx.x; j < BT; j += TPB) {
        const int bi = min(b0 + j, nG - 1);
        const float bx = gt[bi * 4 + 0];
        const float by = gt[bi * 4 + 1];
        const float bz = gt[bi * 4 + 2];
        const float hb = 0.5f * (bx * bx + by * by + bz * bz);
        const int g = j >> 1, l = j & 1, o = g * 8 + l;
        tileF[o + 0] = bx;
        tileF[o + 2] = by;
        tileF[o + 4] = bz;
        tileF[o + 6] = hb;
    }
    __syncthreads();

    float mlo[APT], mhi[APT];
    #pragma unroll
    for (int k = 0; k < APT; k++) { mlo[k] = F32_INF; mhi[k] = F32_INF; }

    unsigned int saddr = (unsigned int)__cvta_generic_to_shared(tileF);

    for (int jb = 0; jb < BT; jb += 8) {
        unsigned long long X01, Y01, Z01, H01, HAB;
        float lo, hi;
        int cl, ch;

        #define GROUP(OX, OZ, JOFF)                                          \
        {                                                                    \
            LDS_V2U64(X01, Y01, saddr, OX);                                  \
            LDS_V2U64(Z01, H01, saddr, OZ);                                  \
            ADD2(HAB, H01, HA[0]);                                           \
            PAIR_DIST(lo, hi, NX[0], NY[0], NZ[0], X01, Y01, Z01, HAB);      \
            mlo[0] = fminf(mlo[0], lo);  mhi[0] = fminf(mhi[0], hi);         \
            cl = __float_as_int(lo);  ch = __float_as_int(hi);               \
            _Pragma("unroll")                                                \
            for (int k = 1; k < APT; k++) {                                  \
                ADD2(HAB, H01, HA[k]);                                       \
                PAIR_DIST(lo, hi, NX[k], NY[k], NZ[k], X01, Y01, Z01, HAB);  \
                mlo[k] = fminf(mlo[k], lo);  mhi[k] = fminf(mhi[k], hi);     \
                cl = min(cl, __float_as_int(lo));                            \
                ch = min(ch, __float_as_int(hi));                            \
            }                                                                \
            cl = redux_min_s32(cl);                                          \
            ch = redux_min_s32(ch);                                          \
            if (lane == 0) {                                                 \
                col_acc[warp][jb + JOFF + 0] = cl;                           \
                col_acc[warp][jb + JOFF + 1] = ch;                           \
            }                                                                \
        }

        GROUP(0,  16, 0)
        GROUP(32, 48, 2)
        GROUP(64, 80, 4)
        GROUP(96, 112, 6)
        #undef GROUP

        saddr += 128;
    }

    // Row partials: min over this B tile for each owned pred point.
    #pragma unroll
    for (int k = 0; k < APT; k++) {
        const int a = a0 + k * TPB;
        if (a < nP)
            g_rmin[blockIdx.y][a] = fminf(mlo[k], mhi[k]);
    }

    // Col partials: combine 8 warps, write this block's B range (int bits).
    __syncthreads();
    for (int j = threadIdx.x; j < BT; j += TPB) {
        int m = col_acc[0][j];
        #pragma unroll
        for (int w = 1; w < 8; w++)
            m = min(m, col_acc[w][j]);
        g_cmin[blockIdx.x][b0 + j] = m;     // padded slots written, never read
    }
}

// Fused row+col partial reduction: blocks [0,redA) handle rows, rest cols.
__global__ __launch_bounds__(TPB)
void cd_red(int nP, int nG, int nbt, int nat, int redA)
{
    float v = 0.f;
    if (blockIdx.x < redA) {
        const int i = blockIdx.x * TPB + threadIdx.x;
        if (i < nP) {
            float m = g_rmin[0][i];
            for (int t = 1; t < nbt; t++)
                m = fminf(m, g_rmin[t][i]);
            v = fmaxf(2.f * m, 0.f) / (float)nP;
        }
    } else {
        const int j = (blockIdx.x - redA) * TPB + threadIdx.x;
        if (j < nG) {
            int m = g_cmin[0][j];
            for (int t = 1; t < nat; t++)
                m = min(m, g_cmin[t][j]);
            v = fmaxf(2.f * __int_as_float(m), 0.f) / (float)nG;
        }
    }
    __shared__ float sm[TPB];
    sm[threadIdx.x] = v;
    __syncthreads();
    for (int s = TPB / 2; s > 0; s >>= 1) {
        if (threadIdx.x < s) sm[threadIdx.x] += sm[threadIdx.x + s];
        __syncthreads();
    }
    if (threadIdx.x == 0) g_bsum[blockIdx.x] = sm[0];
}

__global__ __launch_bounds__(TPB)
void cd_final(float* __restrict__ out, int n)
{
    float v = 0.f;
    for (int i = threadIdx.x; i < n; i += TPB)
        v += g_bsum[i];
    __shared__ float sm[TPB];
    sm[threadIdx.x] = v;
    __syncthreads();
    for (int s = TPB / 2; s > 0; s >>= 1) {
        if (threadIdx.x < s) sm[threadIdx.x] += sm[threadIdx.x + s];
        __syncthreads();
    }
    if (threadIdx.x == 0) out[0] = sm[0];
}

extern "C" void kernel_launch(void* const* d_in, const int* in_sizes, int n_in,
                              void* d_out, int out_size)
{
    // pred has 3 columns (smaller buffer), gt has 4. Robust to input order.
    const float* pred;
    const float* gt;
    int szP, szG;
    if (in_sizes[0] <= in_sizes[1]) {
        pred = (const float*)d_in[0]; szP = in_sizes[0];
        gt   = (const float*)d_in[1]; szG = in_sizes[1];
    } else {
        pred = (const float*)d_in[1]; szP = in_sizes[1];
        gt   = (const float*)d_in[0]; szG = in_sizes[0];
    }
    const int nP = szP / 3;
    const int nG = szG / 4;

    const int atiles = (nP + ABLK - 1) / ABLK;      // 20
    const int btiles = (nG + BT - 1) / BT;          // 74

    dim3 grid(atiles, btiles);
    cd_tile_kernel<<<grid, TPB>>>(pred, nP, gt, nG);

    const int redA = (nP + TPB - 1) / TPB;          // 79
    const int redB = (nG + TPB - 1) / TPB;          // 79
    cd_red<<<redA + redB, TPB>>>(nP, nG, btiles, atiles, redA);
    cd_final<<<1, TPB>>>((float*)d_out, redA + redB);
}

// round 9
// speedup vs baseline: 1.3095x; 1.0491x over previous
#include <cuda_runtime.h>
#include <cstdint>

// Chamfer distance, one-pass shared distance matrix.
// t' = (0.5|a|^2 + 0.5|b|^2) - a.b = d^2/2.  Row mins (over gt) and col mins
// (over pred) reduce the SAME t' values. Col mins cross the warp via
// redux.sync.min.s32 on the float bits: exact for non-negative floats, and any
// negative t' (rounding noise) clamps to 0 in the epilogue regardless of which
// negative wins. redux.s32 is sm_80+ (redux.f32 rejected at compute_100).
//
// R8 model: issue-slot bound at ~60% issue density; suspect MIO (REDUX/LDS/STS)
// throttle. R9: APT 4->8, TPB 256->128 (same ABLK=1024, same 20x74 grid):
// -10% issue slots per pair and HALVED MIO ops per pair.

#define TPB    128
#define NWARP  (TPB / 32)          // 4
#define APT    8                  // pred points per thread
#define ABLK   (TPB * APT)        // 1024 pred points per block
#define BT     272                // gt points per tile (mult of 8); 74 tiles
#define MAXNP  20480              // >= 20000, multiple of ABLK
#define MAXNB  20128              // 74*272 >= 20000
#define MAX_BTILES (MAXNB / BT)   // 74
#define MAX_ATILES (MAXNP / ABLK) // 20
#define RTPB   256
#define MAX_RED  ((MAXNP + RTPB - 1) / RTPB)   // 80

__device__ float g_rmin[MAX_BTILES][MAXNP];
__device__ int   g_cmin[MAX_ATILES][MAXNB];
__device__ float g_bsum[2 * MAX_RED];

#define F32_INF __int_as_float(0x7f800000)

#define LDS_V2U64(v0, v1, base, OFF)                                     \
    asm volatile("ld.shared.v2.u64 {%0,%1}, [%2+" #OFF "];"              \
                 : "=l"(v0), "=l"(v1) : "r"(base))

#define ADD2(out, a, b)                                                  \
    asm("add.rn.f32x2 %0, %1, %2;" : "=l"(out) : "l"(a), "l"(b))

// t = fma(nx, x01, hab); t = fma(ny, y01, t); t = fma(nz, z01, t); unpack.
#define PAIR_DIST(lo, hi, nx, ny, nz, x01, y01, z01, hab)                \
    asm("{\n\t.reg .b64 t;\n\t"                                          \
        "fma.rn.f32x2 t, %2, %3, %8;\n\t"                                \
        "fma.rn.f32x2 t, %4, %5, t;\n\t"                                 \
        "fma.rn.f32x2 t, %6, %7, t;\n\t"                                 \
        "mov.b64 {%0,%1}, t;\n\t}"                                       \
        : "=f"(lo), "=f"(hi)                                             \
        : "l"(nx), "l"(x01), "l"(ny), "l"(y01), "l"(nz), "l"(z01), "l"(hab))

__device__ __forceinline__ int redux_min_s32(int v) {
    int r;
    asm("redux.sync.min.s32 %0, %1, 0xffffffff;" : "=r"(r) : "r"(v));
    return r;
}

__global__ __launch_bounds__(TPB)
void cd_tile_kernel(const float* __restrict__ pred, int nP,
                    const float* __restrict__ gt,   int nG)
{
    __shared__ __align__(16) float tileF[BT * 4];  // per 2 B pts: {x0,x1,y0,y1,z0,z1,h0,h1}
    __shared__ int col_acc[NWARP][BT];             // per-warp col mins (each col written once)

    const int warp = threadIdx.x >> 5;
    const int lane = threadIdx.x & 31;

    // A = pred points, clamped-duplicate padding (dups harmless for col mins;
    // row writes guarded by original index).
    const int a0 = blockIdx.x * ABLK + threadIdx.x;
    unsigned long long NX[APT], NY[APT], NZ[APT], HA[APT];
    #pragma unroll
    for (int k = 0; k < APT; k++) {
        const int ac = min(a0 + k * TPB, nP - 1);
        const float ax = pred[ac * 3 + 0];
        const float ay = pred[ac * 3 + 1];
        const float az = pred[ac * 3 + 2];
        const float nax = -ax, nay = -ay, naz = -az;
        const float ha = 0.5f * (ax * ax + ay * ay + az * az);
        asm("mov.b64 %0, {%1,%1};" : "=l"(NX[k]) : "f"(nax));
        asm("mov.b64 %0, {%1,%1};" : "=l"(NY[k]) : "f"(nay));
        asm("mov.b64 %0, {%1,%1};" : "=l"(NZ[k]) : "f"(naz));
        asm("mov.b64 %0, {%1,%1};" : "=l"(HA[k]) : "f"(ha));
    }

    // B tile = gt points, clamped-duplicate padding.
    const int b0 = blockIdx.y * BT;
    for (int j = threadIdx.x; j < BT; j += TPB) {
        const int bi = min(b0 + j, nG - 1);
        const float bx = gt[bi * 4 + 0];
        const float by = gt[bi * 4 + 1];
        const float bz = gt[bi * 4 + 2];
        const float hb = 0.5f * (bx * bx + by * by + bz * bz);
        const int g = j >> 1, l = j & 1, o = g * 8 + l;
        tileF[o + 0] = bx;
        tileF[o + 2] = by;
        tileF[o + 4] = bz;
        tileF[o + 6] = hb;
    }
    __syncthreads();

    float mlo[APT], mhi[APT];
    #pragma unroll
    for (int k = 0; k < APT; k++) { mlo[k] = F32_INF; mhi[k] = F32_INF; }

    unsigned int saddr = (unsigned int)__cvta_generic_to_shared(tileF);

    for (int jb = 0; jb < BT; jb += 8) {
        unsigned long long X01, Y01, Z01, H01, HAB;
        float lo, hi;
        int cl, ch;

        #define GROUP(OX, OZ, JOFF)                                          \
        {                                                                    \
            LDS_V2U64(X01, Y01, saddr, OX);                                  \
            LDS_V2U64(Z01, H01, saddr, OZ);                                  \
            ADD2(HAB, H01, HA[0]);                                           \
            PAIR_DIST(lo, hi, NX[0], NY[0], NZ[0], X01, Y01, Z01, HAB);      \
            mlo[0] = fminf(mlo[0], lo);  mhi[0] = fminf(mhi[0], hi);         \
            cl = __float_as_int(lo);  ch = __float_as_int(hi);               \
            _Pragma("unroll")                                                \
            for (int k = 1; k < APT; k++) {                                  \
                ADD2(HAB, H01, HA[k]);                                       \
                PAIR_DIST(lo, hi, NX[k], NY[k], NZ[k], X01, Y01, Z01, HAB);  \
                mlo[k] = fminf(mlo[k], lo);  mhi[k] = fminf(mhi[k], hi);     \
                cl = min(cl, __float_as_int(lo));                            \
                ch = min(ch, __float_as_int(hi));                            \
            }                                                                \
            cl = redux_min_s32(cl);                                          \
            ch = redux_min_s32(ch);                                          \
            if (lane == 0) {                                                 \
                col_acc[warp][jb + JOFF + 0] = cl;                           \
                col_acc[warp][jb + JOFF + 1] = ch;                           \
            }                                                                \
        }

        GROUP(0,  16, 0)
        GROUP(32, 48, 2)
        GROUP(64, 80, 4)
        GROUP(96, 112, 6)
        #undef GROUP

        saddr += 128;
    }

    // Row partials: min over this B tile for each owned pred point.
    #pragma unroll
    for (int k = 0; k < APT; k++) {
        const int a = a0 + k * TPB;
        if (a < nP)
            g_rmin[blockIdx.y][a] = fminf(mlo[k], mhi[k]);
    }

    // Col partials: combine NWARP warps, write this block's B range (int bits).
    __syncthreads();
    for (int j = threadIdx.x; j < BT; j += TPB) {
        int m = col_acc[0][j];
        #pragma unroll
        for (int w = 1; w < NWARP; w++)
            m = min(m, col_acc[w][j]);
        g_cmin[blockIdx.x][b0 + j] = m;     // padded slots written, never read
    }
}

// Fused row+col partial reduction: blocks [0,redA) handle rows, rest cols.
__global__ __launch_bounds__(RTPB)
void cd_red(int nP, int nG, int nbt, int nat, int redA)
{
    float v = 0.f;
    if (blockIdx.x < redA) {
        const int i = blockIdx.x * RTPB + threadIdx.x;
        if (i < nP) {
            float m = g_rmin[0][i];
            for (int t = 1; t < nbt; t++)
                m = fminf(m, g_rmin[t][i]);
            v = fmaxf(2.f * m, 0.f) / (float)nP;
        }
    } else {
        const int j = (blockIdx.x - redA) * RTPB + threadIdx.x;
        if (j < nG) {
            int m = g_cmin[0][j];
            for (int t = 1; t < nat; t++)
                m = min(m, g_cmin[t][j]);
            v = fmaxf(2.f * __int_as_float(m), 0.f) / (float)nG;
        }
    }
    __shared__ float sm[RTPB];
    sm[threadIdx.x] = v;
    __syncthreads();
    for (int s = RTPB / 2; s > 0; s >>= 1) {
        if (threadIdx.x < s) sm[threadIdx.x] += sm[threadIdx.x + s];
        __syncthreads();
    }
    if (threadIdx.x == 0) g_bsum[blockIdx.x] = sm[0];
}

__global__ __launch_bounds__(RTPB)
void cd_final(float* __restrict__ out, int n)
{
    float v = 0.f;
    for (int i = threadIdx.x; i < n; i += RTPB)
        v += g_bsum[i];
    __shared__ float sm[RTPB];
    sm[threadIdx.x] = v;
    __syncthreads();
    for (int s = RTPB / 2; s > 0; s >>= 1) {
        if (threadIdx.x < s) sm[threadIdx.x] += sm[threadIdx.x + s];
        __syncthreads();
    }
    if (threadIdx.x == 0) out[0] = sm[0];
}

extern "C" void kernel_launch(void* const* d_in, const int* in_sizes, int n_in,
                              void* d_out, int out_size)
{
    // pred has 3 columns (smaller buffer), gt has 4. Robust to input order.
    const float* pred;
    const float* gt;
    int szP, szG;
    if (in_sizes[0] <= in_sizes[1]) {
        pred = (const float*)d_in[0]; szP = in_sizes[0];
        gt   = (const float*)d_in[1]; szG = in_sizes[1];
    } else {
        pred = (const float*)d_in[1]; szP = in_sizes[1];
        gt   = (const float*)d_in[0]; szG = in_sizes[0];
    }
    const int nP = szP / 3;
    const int nG = szG / 4;

    const int atiles = (nP + ABLK - 1) / ABLK;      // 20
    const int btiles = (nG + BT - 1) / BT;          // 74

    dim3 grid(atiles, btiles);
    cd_tile_kernel<<<grid, TPB>>>(pred, nP, gt, nG);

    const int redA = (nP + RTPB - 1) / RTPB;        // 79
    const int redB = (nG + RTPB - 1) / RTPB;        // 79
    cd_red<<<redA + redB, RTPB>>>(nP, nG, btiles, atiles, redA);
    cd_final<<<1, RTPB>>>((float*)d_out, redA + redB);
}

// round 14
// speedup vs baseline: 1.4316x; 1.0932x over previous
#include <cuda_runtime.h>
#include <cstdint>

// Chamfer distance, one-pass shared distance matrix.
// t' = (0.5|a|^2 + 0.5|b|^2) - a.b = d^2/2.  Row mins (over gt) and col mins
// (over pred) reduce the SAME t' values. Col mins cross the warp via
// redux.sync.min.s32 on float bits (exact here: negatives clamp to 0 later).
//
// R10: min.f32x2 doesn't exist -> scalar min slots are an ISA floor; kernel is
// issue-density bound (55%) with exposed LDS latency at each group start.
// R14 (= R12/R13 resubmit; containers failed): software-pipeline the B loads
// (ping-pong register prefetch, padded tile).

#define TPB    128
#define NWARP  (TPB / 32)          // 4
#define APT    8                  // pred points per thread
#define ABLK   (TPB * APT)        // 1024 pred points per block
#define BT     272                // gt points per tile (mult of 4); 74 tiles
#define BTP    (BT + 4)           // padded for branchless prefetch overrun
#define MAXNP  20480              // >= 20000, multiple of ABLK
#define MAXNB  20128              // 74*272 >= 20000
#define MAX_BTILES (MAXNB / BT)   // 74
#define MAX_ATILES (MAXNP / ABLK) // 20
#define RTPB   256
#define MAX_RED  ((MAXNP + RTPB - 1) / RTPB)   // 80

__device__ float g_rmin[MAX_BTILES][MAXNP];
__device__ int   g_cmin[MAX_ATILES][MAXNB];
__device__ float g_bsum[2 * MAX_RED];

#define F32_INF __int_as_float(0x7f800000)

#define LDS_V2U64(v0, v1, base, OFF)                                     \
    asm volatile("ld.shared.v2.u64 {%0,%1}, [%2+" #OFF "];"              \
                 : "=l"(v0), "=l"(v1) : "r"(base))

#define ADD2(out, a, b)                                                  \
    asm("add.rn.f32x2 %0, %1, %2;" : "=l"(out) : "l"(a), "l"(b))

// t = fma(nx, x01, hab); t = fma(ny, y01, t); t = fma(nz, z01, t); unpack.
#define PAIR_DIST(lo, hi, nx, ny, nz, x01, y01, z01, hab)                \
    asm("{\n\t.reg .b64 t;\n\t"                                          \
        "fma.rn.f32x2 t, %2, %3, %8;\n\t"                                \
        "fma.rn.f32x2 t, %4, %5, t;\n\t"                                 \
        "fma.rn.f32x2 t, %6, %7, t;\n\t"                                 \
        "mov.b64 {%0,%1}, t;\n\t}"                                       \
        : "=f"(lo), "=f"(hi)                                             \
        : "l"(nx), "l"(x01), "l"(ny), "l"(y01), "l"(nz), "l"(z01), "l"(hab))

__device__ __forceinline__ int redux_min_s32(int v) {
    int r;
    asm("redux.sync.min.s32 %0, %1, 0xffffffff;" : "=r"(r) : "r"(v));
    return r;
}

__global__ __launch_bounds__(TPB)
void cd_tile_kernel(const float* __restrict__ pred, int nP,
                    const float* __restrict__ gt,   int nG)
{
    __shared__ __align__(16) float tileF[BTP * 4]; // per 2 B pts: {x0,x1,y0,y1,z0,z1,h0,h1}
    __shared__ int col_acc[NWARP][BT];             // per-warp col mins (each col written once)

    const int warp = threadIdx.x >> 5;
    const int lane = threadIdx.x & 31;

    // A = pred points, clamped-duplicate padding (dups harmless for col mins;
    // row writes guarded by original index).
    const int a0 = blockIdx.x * ABLK + threadIdx.x;
    unsigned long long NX[APT], NY[APT], NZ[APT], HA[APT];
    #pragma unroll
    for (int k = 0; k < APT; k++) {
        const int ac = min(a0 + k * TPB, nP - 1);
        const float ax = pred[ac * 3 + 0];
        const float ay = pred[ac * 3 + 1];
        const float az = pred[ac * 3 + 2];
        const float nax = -ax, nay = -ay, naz = -az;
        const float ha = 0.5f * (ax * ax + ay * ay + az * az);
        asm("mov.b64 %0, {%1,%1};" : "=l"(NX[k]) : "f"(nax));
        asm("mov.b64 %0, {%1,%1};" : "=l"(NY[k]) : "f"(nay));
        asm("mov.b64 %0, {%1,%1};" : "=l"(NZ[k]) : "f"(naz));
        asm("mov.b64 %0, {%1,%1};" : "=l"(HA[k]) : "f"(ha));
    }

    // B tile = gt points; pad BOTH the tail-of-data and the prefetch overrun
    // region with copies of the last point.
    const int b0 = blockIdx.y * BT;
    for (int j = threadIdx.x; j < BTP; j += TPB) {
        const int bi = min(b0 + min(j, BT - 1), nG - 1);
        const float bx = gt[bi * 4 + 0];
        const float by = gt[bi * 4 + 1];
        const float bz = gt[bi * 4 + 2];
        const float hb = 0.5f * (bx * bx + by * by + bz * bz);
        const int g = j >> 1, l = j & 1, o = g * 8 + l;
        tileF[o + 0] = bx;
        tileF[o + 2] = by;
        tileF[o + 4] = bz;
        tileF[o + 6] = hb;
    }
    __syncthreads();

    float mlo[APT], mhi[APT];
    #pragma unroll
    for (int k = 0; k < APT; k++) { mlo[k] = F32_INF; mhi[k] = F32_INF; }

    unsigned int saddr = (unsigned int)__cvta_generic_to_shared(tileF);

    // GROUP: process one prefetched B pair (2 columns), scalar-min paths.
    #define GROUP(XR, YR, ZR, HR, COL)                                       \
    {                                                                        \
        unsigned long long HAB;                                              \
        float lo, hi;                                                        \
        int cl, ch;                                                          \
        ADD2(HAB, HR, HA[0]);                                                \
        PAIR_DIST(lo, hi, NX[0], NY[0], NZ[0], XR, YR, ZR, HAB);             \
        mlo[0] = fminf(mlo[0], lo);  mhi[0] = fminf(mhi[0], hi);             \
        cl = __float_as_int(lo);  ch = __float_as_int(hi);                   \
        _Pragma("unroll")                                                    \
        for (int k = 1; k < APT; k++) {                                      \
            ADD2(HAB, HR, HA[k]);                                            \
            PAIR_DIST(lo, hi, NX[k], NY[k], NZ[k], XR, YR, ZR, HAB);         \
            mlo[k] = fminf(mlo[k], lo);  mhi[k] = fminf(mhi[k], hi);         \
            cl = min(cl, __float_as_int(lo));                                \
            ch = min(ch, __float_as_int(hi));                                \
        }                                                                    \
        cl = redux_min_s32(cl);                                              \
        ch = redux_min_s32(ch);                                              \
        if (lane == 0) {                                                     \
            col_acc[warp][(COL) + 0] = cl;                                   \
            col_acc[warp][(COL) + 1] = ch;                                   \
        }                                                                    \
    }

    {
        unsigned long long X0, Y0, Z0, H0, X1, Y1, Z1, H1;
        LDS_V2U64(X0, Y0, saddr, 0);
        LDS_V2U64(Z0, H0, saddr, 16);
        for (int jb = 0; jb < BT; jb += 4) {
            LDS_V2U64(X1, Y1, saddr, 32);       // prefetch group g+1
            LDS_V2U64(Z1, H1, saddr, 48);
            GROUP(X0, Y0, Z0, H0, jb + 0)
            LDS_V2U64(X0, Y0, saddr, 64);       // prefetch group g+2 (pad-safe)
            LDS_V2U64(Z0, H0, saddr, 80);
            GROUP(X1, Y1, Z1, H1, jb + 2)
            saddr += 64;
        }
    }
    #undef GROUP

    // Row partials: min over this B tile for each owned pred point.
    #pragma unroll
    for (int k = 0; k < APT; k++) {
        const int a = a0 + k * TPB;
        if (a < nP)
            g_rmin[blockIdx.y][a] = fminf(mlo[k], mhi[k]);
    }

    // Col partials: combine NWARP warps, write this block's B range (int bits).
    __syncthreads();
    for (int j = threadIdx.x; j < BT; j += TPB) {
        int m = col_acc[0][j];
        #pragma unroll
        for (int w = 1; w < NWARP; w++)
            m = min(m, col_acc[w][j]);
        g_cmin[blockIdx.x][b0 + j] = m;     // padded slots written, never read
    }
}

// Fused row+col partial reduction: blocks [0,redA) handle rows, rest cols.
__global__ __launch_bounds__(RTPB)
void cd_red(int nP, int nG, int nbt, int nat, int redA)
{
    float v = 0.f;
    if (blockIdx.x < redA) {
        const int i = blockIdx.x * RTPB + threadIdx.x;
        if (i < nP) {
            float m = g_rmin[0][i];
            for (int t = 1; t < nbt; t++)
                m = fminf(m, g_rmin[t][i]);
            v = fmaxf(2.f * m, 0.f) / (float)nP;
        }
    } else {
        const int j = (blockIdx.x - redA) * RTPB + threadIdx.x;
        if (j < nG) {
            int m = g_cmin[0][j];
            for (int t = 1; t < nat; t++)
                m = min(m, g_cmin[t][j]);
            v = fmaxf(2.f * __int_as_float(m), 0.f) / (float)nG;
        }
    }
    __shared__ float sm[RTPB];
    sm[threadIdx.x] = v;
    __syncthreads();
    for (int s = RTPB / 2; s > 0; s >>= 1) {
        if (threadIdx.x < s) sm[threadIdx.x] += sm[threadIdx.x + s];
        __syncthreads();
    }
    if (threadIdx.x == 0) g_bsum[blockIdx.x] = sm[0];
}

__global__ __launch_bounds__(RTPB)
void cd_final(float* __restrict__ out, int n)
{
    float v = 0.f;
    for (int i = threadIdx.x; i < n; i += RTPB)
        v += g_bsum[i];
    __shared__ float sm[RTPB];
    sm[threadIdx.x] = v;
    __syncthreads();
    for (int s = RTPB / 2; s > 0; s >>= 1) {
        if (threadIdx.x < s) sm[threadIdx.x] += sm[threadIdx.x + s];
        __syncthreads();
    }
    if (threadIdx.x == 0) out[0] = sm[0];
}

extern "C" void kernel_launch(void* const* d_in, const int* in_sizes, int n_in,
                              void* d_out, int out_size)
{
    // pred has 3 columns (smaller buffer), gt has 4. Robust to input order.
    const float* pred;
    const float* gt;
    int szP, szG;
    if (in_sizes[0] <= in_sizes[1]) {
        pred = (const float*)d_in[0]; szP = in_sizes[0];
        gt   = (const float*)d_in[1]; szG = in_sizes[1];
    } else {
        pred = (const float*)d_in[1]; szP = in_sizes[1];
        gt   = (const float*)d_in[0]; szG = in_sizes[0];
    }
    const int nP = szP / 3;
    const int nG = szG / 4;

    const int atiles = (nP + ABLK - 1) / ABLK;      // 20
    const int btiles = (nG + BT - 1) / BT;          // 74

    dim3 grid(atiles, btiles);
    cd_tile_kernel<<<grid, TPB>>>(pred, nP, gt, nG);

    const int redA = (nP + RTPB - 1) / RTPB;        // 79
    const int redB = (nG + RTPB - 1) / RTPB;        // 79
    cd_red<<<redA + redB, RTPB>>>(nP, nG, btiles, atiles, redA);
    cd_final<<<1, RTPB>>>((float*)d_out, redA + redB);
}